// round 5
// baseline (speedup 1.0000x reference)
#include <cuda_runtime.h>

// NeuralODE fused RK4 persistent kernel, f32x2-packed FFMA version.
// B=1024, D=256, H=1024, 8 RK4 steps (32 MLP evals).
// 128 CTAs x 256 threads; each CTA integrates 8 batch rows start-to-finish.
// Weights (2 MB) stream from L2 each eval. Math uses fma.rn.f32x2 packed
// over adjacent output columns: weight pairs come free from LDG.128 halves,
// only the broadcast scalar needs a mov.b64 {r,r} duplication.

namespace {
constexpr int Bn     = 1024;
constexpr int Dn     = 256;
constexpr int Hn     = 1024;
constexpr int NSTEPS = 8;
constexpr int MBLK   = 8;
constexpr int NTHR   = 256;
constexpr int GRID   = Bn / MBLK;   // 128 CTAs
}

using ull = unsigned long long;

__device__ __forceinline__ float tanha(float x) {
    float y;
    asm("tanh.approx.f32 %0, %1;" : "=f"(y) : "f"(x));
    return y;
}

// pack {x, x} into a b64 f32x2 register
__device__ __forceinline__ ull dup2(float x) {
    ull r;
    asm("mov.b64 %0, {%1, %1};" : "=l"(r) : "f"(x));
    return r;
}

// pack {lo, hi}
__device__ __forceinline__ ull pk2(float lo, float hi) {
    ull r;
    asm("mov.b64 %0, {%1, %2};" : "=l"(r) : "f"(lo), "f"(hi));
    return r;
}

// unpack b64 -> two floats
__device__ __forceinline__ void unpk2(ull p, float& lo, float& hi) {
    asm("mov.b64 {%0, %1}, %2;" : "=f"(lo), "=f"(hi) : "l"(p));
}

// d = a * b + c, elementwise on packed f32x2
__device__ __forceinline__ ull fma2(ull a, ull b, ull c) {
    ull d;
    asm("fma.rn.f32x2 %0, %1, %2, %3;" : "=l"(d) : "l"(a), "l"(b), "l"(c));
    return d;
}

__device__ __forceinline__ float4 f4_axpy(float a, float4 x, float4 y) {
    float4 r;
    r.x = fmaf(a, x.x, y.x);
    r.y = fmaf(a, x.y, y.y);
    r.z = fmaf(a, x.z, y.z);
    r.w = fmaf(a, x.w, y.w);
    return r;
}

__device__ __forceinline__ float4 f4_add(float4 a, float4 b) {
    float4 r; r.x = a.x + b.x; r.y = a.y + b.y; r.z = a.z + b.z; r.w = a.w + b.w; return r;
}

__global__ void __launch_bounds__(NTHR, 1) node_rk4_kernel(
    const float* __restrict__ z0, const float* __restrict__ tt,
    const float* __restrict__ W1, const float* __restrict__ b1,
    const float* __restrict__ W2, const float* __restrict__ b2,
    float* __restrict__ out)
{
    __shared__ __align__(16) float s_probe[MBLK][Dn];   //  8 KB
    __shared__ __align__(16) float s_hid[MBLK][Hn];     // 32 KB

    const int tid  = threadIdx.x;
    const int row0 = blockIdx.x * MBLK;

    const float h  = (tt[1] - tt[0]) / (float)NSTEPS;
    const float h2 = 0.5f * h;
    const float h6 = h * (1.0f / 6.0f);

    // phase-1 ownership: 8 hidden cols x 4 rows
    const int jc  = tid & 127;        // col block: cols [8*jc, 8*jc+8)
    const int mg4 = (tid >> 7) * 4;   // rows [mg4, mg4+4)
    // phase-2 / glue ownership: 4 out cols x 2 rows (m0, m0+4)
    const int iw = tid & 63;          // cols [4*iw, 4*iw+4)
    const int m0 = tid >> 6;

    const ulonglong2* __restrict__ W1u2 = reinterpret_cast<const ulonglong2*>(W1);
    const ulonglong2* __restrict__ W2u2 = reinterpret_cast<const ulonglong2*>(W2);

    // biases (packed pairs), loaded once
    const float4 b1a = reinterpret_cast<const float4*>(b1)[2 * jc];
    const float4 b1b = reinterpret_cast<const float4*>(b1)[2 * jc + 1];
    const ull b1p0 = pk2(b1a.x, b1a.y), b1p1 = pk2(b1a.z, b1a.w);
    const ull b1p2 = pk2(b1b.x, b1b.y), b1p3 = pk2(b1b.z, b1b.w);
    const float4 b2v = reinterpret_cast<const float4*>(b2)[iw];
    const ull b2p0 = pk2(b2v.x, b2v.y), b2p1 = pk2(b2v.z, b2v.w);

    // z_base in registers (phase-2 ownership), mirrored into s_probe
    float4 zb0 = reinterpret_cast<const float4*>(z0)[(row0 + m0)     * (Dn / 4) + iw];
    float4 zb1 = reinterpret_cast<const float4*>(z0)[(row0 + m0 + 4) * (Dn / 4) + iw];
    *reinterpret_cast<float4*>(&s_probe[m0][4 * iw])     = zb0;
    *reinterpret_cast<float4*>(&s_probe[m0 + 4][4 * iw]) = zb1;
    __syncthreads();

    float4 ac0, ac1;  // RK4 accumulators

// one sub-d of phase 1: weights for 8 cols, dup'd z scalar per row, 16 FFMA2
#define P1STEP(comp, dof)                                                       \
    do {                                                                        \
        const ulonglong2 wa = W1u2[(dbase + (dof)) * (Hn / 4) + 2 * jc];        \
        const ulonglong2 wb = W1u2[(dbase + (dof)) * (Hn / 4) + 2 * jc + 1];    \
        const ull zd0 = dup2(zr0.comp);                                         \
        const ull zd1 = dup2(zr1.comp);                                         \
        const ull zd2 = dup2(zr2.comp);                                         \
        const ull zd3 = dup2(zr3.comp);                                         \
        ac00 = fma2(zd0, wa.x, ac00); ac01 = fma2(zd0, wa.y, ac01);             \
        ac02 = fma2(zd0, wb.x, ac02); ac03 = fma2(zd0, wb.y, ac03);             \
        ac10 = fma2(zd1, wa.x, ac10); ac11 = fma2(zd1, wa.y, ac11);             \
        ac12 = fma2(zd1, wb.x, ac12); ac13 = fma2(zd1, wb.y, ac13);             \
        ac20 = fma2(zd2, wa.x, ac20); ac21 = fma2(zd2, wa.y, ac21);             \
        ac22 = fma2(zd2, wb.x, ac22); ac23 = fma2(zd2, wb.y, ac23);             \
        ac30 = fma2(zd3, wa.x, ac30); ac31 = fma2(zd3, wa.y, ac31);             \
        ac32 = fma2(zd3, wb.x, ac32); ac33 = fma2(zd3, wb.y, ac33);             \
    } while (0)

// tanh epilogue for one row: unpack 4 pairs -> 8 tanh -> 2 x STS.128
#define P1EPI(pA, pB, pC, pD, rowi)                                             \
    do {                                                                        \
        float u0, u1, u2, u3, u4, u5, u6, u7;                                   \
        unpk2(pA, u0, u1); unpk2(pB, u2, u3);                                   \
        unpk2(pC, u4, u5); unpk2(pD, u6, u7);                                   \
        const float4 ta = make_float4(tanha(u0), tanha(u1), tanha(u2), tanha(u3)); \
        const float4 tb = make_float4(tanha(u4), tanha(u5), tanha(u6), tanha(u7)); \
        *reinterpret_cast<float4*>(&s_hid[mg4 + (rowi)][8 * jc])     = ta;      \
        *reinterpret_cast<float4*>(&s_hid[mg4 + (rowi)][8 * jc + 4]) = tb;      \
    } while (0)

// one sub-j of phase 2: weight pair from LDG.128 halves, dup'd hid scalars
#define P2STEP(comp, jof)                                                       \
    do {                                                                        \
        const ulonglong2 wv = W2u2[(jbase + (jof)) * (Dn / 4) + iw];            \
        const ull hd0 = dup2(hv0.comp);                                         \
        const ull hd1 = dup2(hv1.comp);                                         \
        k00 = fma2(hd0, wv.x, k00); k01 = fma2(hd0, wv.y, k01);                 \
        k10 = fma2(hd1, wv.x, k10); k11 = fma2(hd1, wv.y, k11);                 \
    } while (0)

    for (int step = 0; step < NSTEPS; ++step) {
        #pragma unroll
        for (int e = 0; e < 4; ++e) {
            // ---------- phase 1: hid = tanh(probe @ W1 + b1) ----------
            ull ac00 = b1p0, ac01 = b1p1, ac02 = b1p2, ac03 = b1p3;
            ull ac10 = b1p0, ac11 = b1p1, ac12 = b1p2, ac13 = b1p3;
            ull ac20 = b1p0, ac21 = b1p1, ac22 = b1p2, ac23 = b1p3;
            ull ac30 = b1p0, ac31 = b1p1, ac32 = b1p2, ac33 = b1p3;

            #pragma unroll 2
            for (int d4 = 0; d4 < Dn / 4; ++d4) {
                const int dbase = d4 * 4;
                const float4 zr0 = *reinterpret_cast<const float4*>(&s_probe[mg4 + 0][dbase]);
                const float4 zr1 = *reinterpret_cast<const float4*>(&s_probe[mg4 + 1][dbase]);
                const float4 zr2 = *reinterpret_cast<const float4*>(&s_probe[mg4 + 2][dbase]);
                const float4 zr3 = *reinterpret_cast<const float4*>(&s_probe[mg4 + 3][dbase]);
                P1STEP(x, 0);
                P1STEP(y, 1);
                P1STEP(z, 2);
                P1STEP(w, 3);
            }

            P1EPI(ac00, ac01, ac02, ac03, 0);
            P1EPI(ac10, ac11, ac12, ac13, 1);
            P1EPI(ac20, ac21, ac22, ac23, 2);
            P1EPI(ac30, ac31, ac32, ac33, 3);
            __syncthreads();

            // ---------- phase 2: k = hid @ W2 + b2 ----------
            ull k00 = b2p0, k01 = b2p1;   // row m0,  cols [4iw, 4iw+4)
            ull k10 = b2p0, k11 = b2p1;   // row m0+4
            #pragma unroll 2
            for (int j4 = 0; j4 < Hn / 4; ++j4) {
                const int jbase = j4 * 4;
                const float4 hv0 = *reinterpret_cast<const float4*>(&s_hid[m0][jbase]);
                const float4 hv1 = *reinterpret_cast<const float4*>(&s_hid[m0 + 4][jbase]);
                P2STEP(x, 0);
                P2STEP(y, 1);
                P2STEP(z, 2);
                P2STEP(w, 3);
            }

            float4 k0, k1;
            unpk2(k00, k0.x, k0.y); unpk2(k01, k0.z, k0.w);
            unpk2(k10, k1.x, k1.y); unpk2(k11, k1.z, k1.w);

            // ---------- RK4 elementwise glue (registers only) ----------
            float4 p0, p1;
            if (e == 0) {
                ac0 = k0;                       ac1 = k1;
                p0  = f4_axpy(h2, k0, zb0);     p1  = f4_axpy(h2, k1, zb1);
            } else if (e == 1) {
                ac0 = f4_axpy(2.0f, k0, ac0);   ac1 = f4_axpy(2.0f, k1, ac1);
                p0  = f4_axpy(h2, k0, zb0);     p1  = f4_axpy(h2, k1, zb1);
            } else if (e == 2) {
                ac0 = f4_axpy(2.0f, k0, ac0);   ac1 = f4_axpy(2.0f, k1, ac1);
                p0  = f4_axpy(h, k0, zb0);      p1  = f4_axpy(h, k1, zb1);
            } else {
                ac0 = f4_add(ac0, k0);          ac1 = f4_add(ac1, k1);
                zb0 = f4_axpy(h6, ac0, zb0);    zb1 = f4_axpy(h6, ac1, zb1);
                p0  = zb0;                      p1  = zb1;
            }
            *reinterpret_cast<float4*>(&s_probe[m0][4 * iw])     = p0;
            *reinterpret_cast<float4*>(&s_probe[m0 + 4][4 * iw]) = p1;
            __syncthreads();
        }
    }

    reinterpret_cast<float4*>(out)[(row0 + m0)     * (Dn / 4) + iw] = zb0;
    reinterpret_cast<float4*>(out)[(row0 + m0 + 4) * (Dn / 4) + iw] = zb1;

#undef P1STEP
#undef P1EPI
#undef P2STEP
}

extern "C" void kernel_launch(void* const* d_in, const int* in_sizes, int n_in,
                              void* d_out, int out_size) {
    const float* z0 = (const float*)d_in[0];
    const float* tt = (const float*)d_in[1];
    const float* W1 = (const float*)d_in[2];
    const float* b1 = (const float*)d_in[3];
    const float* W2 = (const float*)d_in[4];
    const float* b2 = (const float*)d_in[5];
    float* out = (float*)d_out;
    (void)in_sizes; (void)n_in; (void)out_size;

    node_rk4_kernel<<<GRID, NTHR>>>(z0, tt, W1, b1, W2, b2, out);
}

// round 6
// speedup vs baseline: 1.5262x; 1.5262x over previous
#include <cuda_runtime.h>

// NeuralODE fused RK4 persistent kernel — L1-datapath-optimized f32x2 version.
// B=1024, D=256, H=1024, 8 RK4 steps (32 MLP evals). 128 CTAs x 256 threads.
//
// Per-eval weight traffic per CTA (the R5 bottleneck):
//   phase1: W1 read exactly once (1 MB)   [was 2 MB]
//   phase2: W2 read twice (2 MB)          [was 4 MB]  (2 row-groups; j-range
//           split across half-warps, partials reduced with shfl.xor(16))
// Activations (probe/hid) read via warp-broadcast LDS.

namespace {
constexpr int Bn     = 1024;
constexpr int Dn     = 256;
constexpr int Hn     = 1024;
constexpr int NSTEPS = 8;
constexpr int MBLK   = 8;
constexpr int NTHR   = 256;
constexpr int GRID   = Bn / MBLK;   // 128 CTAs
}

using ull = unsigned long long;

__device__ __forceinline__ float tanha(float x) {
    float y;
    asm("tanh.approx.f32 %0, %1;" : "=f"(y) : "f"(x));
    return y;
}

__device__ __forceinline__ ull dup2(float x) {
    ull r;
    asm("mov.b64 %0, {%1, %1};" : "=l"(r) : "f"(x));
    return r;
}

__device__ __forceinline__ ull pk2(float lo, float hi) {
    ull r;
    asm("mov.b64 %0, {%1, %2};" : "=l"(r) : "f"(lo), "f"(hi));
    return r;
}

__device__ __forceinline__ void unpk2(ull p, float& lo, float& hi) {
    asm("mov.b64 {%0, %1}, %2;" : "=f"(lo), "=f"(hi) : "l"(p));
}

__device__ __forceinline__ ull fma2(ull a, ull b, ull c) {
    ull d;
    asm("fma.rn.f32x2 %0, %1, %2, %3;" : "=l"(d) : "l"(a), "l"(b), "l"(c));
    return d;
}

__device__ __forceinline__ ull add2(ull a, ull b) {
    ull d;
    asm("add.rn.f32x2 %0, %1, %2;" : "=l"(d) : "l"(a), "l"(b));
    return d;
}

__device__ __forceinline__ float4 f4_axpy(float a, float4 x, float4 y) {
    float4 r;
    r.x = fmaf(a, x.x, y.x);
    r.y = fmaf(a, x.y, y.y);
    r.z = fmaf(a, x.z, y.z);
    r.w = fmaf(a, x.w, y.w);
    return r;
}

__device__ __forceinline__ float4 f4_add(float4 a, float4 b) {
    float4 r; r.x = a.x + b.x; r.y = a.y + b.y; r.z = a.z + b.z; r.w = a.w + b.w; return r;
}

__global__ void __launch_bounds__(NTHR, 1) node_rk4_kernel(
    const float* __restrict__ z0, const float* __restrict__ tt,
    const float* __restrict__ W1, const float* __restrict__ b1,
    const float* __restrict__ W2, const float* __restrict__ b2,
    float* __restrict__ out)
{
    __shared__ __align__(16) float s_probe[MBLK][Dn];   //  8 KB
    __shared__ __align__(16) float s_hid[MBLK][Hn];     // 32 KB

    const int tid  = threadIdx.x;
    const int row0 = blockIdx.x * MBLK;

    const float h  = (tt[1] - tt[0]) / (float)NSTEPS;
    const float h2 = 0.5f * h;
    const float h6 = h * (1.0f / 6.0f);

    // ---- phase-2 / glue ownership ----
    // warp w, lane l:  q = l>>4 (j-half), cg = l&15.
    // rows: rg = w>>2 -> rows [4*rg, 4*rg+4)
    // cols: i0 = 4*(16*(w&3) + cg)   (4 consecutive output cols)
    const int warp = tid >> 5;
    const int lane = tid & 31;
    const int q    = lane >> 4;            // j-half: [512*q, 512*q+512)
    const int cg   = lane & 15;
    const int rg   = warp >> 2;            // row group (0 or 1)
    const int wq   = warp & 3;
    const int icol = 16 * wq + cg;         // float4 col index (0..63)

    const ulonglong2* __restrict__ W1u2 = reinterpret_cast<const ulonglong2*>(W1);
    const ulonglong2* __restrict__ W2u2 = reinterpret_cast<const ulonglong2*>(W2);

    // biases
    const float4 b1v = reinterpret_cast<const float4*>(b1)[tid];   // phase1 cols 4*tid..
    const ull b1p0 = pk2(b1v.x, b1v.y), b1p1 = pk2(b1v.z, b1v.w);
    const float4 b2v = reinterpret_cast<const float4*>(b2)[icol];
    const ull b2p0 = pk2(b2v.x, b2v.y), b2p1 = pk2(b2v.z, b2v.w);

    // z_base (phase-2 ownership: 4 rows x 4 cols), duplicated across q
    float4 zb[4], ac[4];
    #pragma unroll
    for (int r = 0; r < 4; ++r) {
        zb[r] = reinterpret_cast<const float4*>(z0)[(row0 + 4 * rg + r) * (Dn / 4) + icol];
        *reinterpret_cast<float4*>(&s_probe[4 * rg + r][4 * icol]) = zb[r];
    }
    __syncthreads();

// ---- phase 1 sub-step: one d value (component `comp` of zr, offset `dof`) ----
// weights for this thread's 4 cols come as one ulonglong2 (2 f32x2 pairs).
#define P1STEP(comp, dof)                                                        \
    do {                                                                         \
        const ulonglong2 wv = W1u2[(dbase + (dof)) * (Hn / 4) + tid];            \
        ull zd;                                                                  \
        zd = dup2(zr0.comp); a00 = fma2(zd, wv.x, a00); a01 = fma2(zd, wv.y, a01); \
        zd = dup2(zr1.comp); a10 = fma2(zd, wv.x, a10); a11 = fma2(zd, wv.y, a11); \
        zd = dup2(zr2.comp); a20 = fma2(zd, wv.x, a20); a21 = fma2(zd, wv.y, a21); \
        zd = dup2(zr3.comp); a30 = fma2(zd, wv.x, a30); a31 = fma2(zd, wv.y, a31); \
        zd = dup2(zr4.comp); a40 = fma2(zd, wv.x, a40); a41 = fma2(zd, wv.y, a41); \
        zd = dup2(zr5.comp); a50 = fma2(zd, wv.x, a50); a51 = fma2(zd, wv.y, a51); \
        zd = dup2(zr6.comp); a60 = fma2(zd, wv.x, a60); a61 = fma2(zd, wv.y, a61); \
        zd = dup2(zr7.comp); a70 = fma2(zd, wv.x, a70); a71 = fma2(zd, wv.y, a71); \
    } while (0)

#define P1EPI(pA, pB, rowi)                                                      \
    do {                                                                         \
        float u0, u1, u2, u3;                                                    \
        unpk2(pA, u0, u1); unpk2(pB, u2, u3);                                    \
        const float4 tv = make_float4(tanha(u0), tanha(u1), tanha(u2), tanha(u3)); \
        *reinterpret_cast<float4*>(&s_hid[(rowi)][4 * tid]) = tv;                \
    } while (0)

// ---- phase 2 sub-step: one j value ----
#define P2STEP(comp, jof)                                                        \
    do {                                                                         \
        const ulonglong2 wv = W2u2[(jbase + (jof)) * (Dn / 4) + icol];           \
        ull hd;                                                                  \
        hd = dup2(hv0.comp); k00 = fma2(hd, wv.x, k00); k01 = fma2(hd, wv.y, k01); \
        hd = dup2(hv1.comp); k10 = fma2(hd, wv.x, k10); k11 = fma2(hd, wv.y, k11); \
        hd = dup2(hv2.comp); k20 = fma2(hd, wv.x, k20); k21 = fma2(hd, wv.y, k21); \
        hd = dup2(hv3.comp); k30 = fma2(hd, wv.x, k30); k31 = fma2(hd, wv.y, k31); \
    } while (0)

    for (int step = 0; step < NSTEPS; ++step) {
        #pragma unroll
        for (int e = 0; e < 4; ++e) {
            // ---------- phase 1: hid = tanh(probe @ W1 + b1) ----------
            // thread owns H-cols [4*tid, 4*tid+4), ALL 8 rows (W1 read once/CTA).
            ull a00 = b1p0, a01 = b1p1, a10 = b1p0, a11 = b1p1;
            ull a20 = b1p0, a21 = b1p1, a30 = b1p0, a31 = b1p1;
            ull a40 = b1p0, a41 = b1p1, a50 = b1p0, a51 = b1p1;
            ull a60 = b1p0, a61 = b1p1, a70 = b1p0, a71 = b1p1;

            #pragma unroll 2
            for (int d4 = 0; d4 < Dn / 4; ++d4) {
                const int dbase = d4 * 4;
                // probe rows: warp-uniform address -> LDS broadcast
                const float4 zr0 = *reinterpret_cast<const float4*>(&s_probe[0][dbase]);
                const float4 zr1 = *reinterpret_cast<const float4*>(&s_probe[1][dbase]);
                const float4 zr2 = *reinterpret_cast<const float4*>(&s_probe[2][dbase]);
                const float4 zr3 = *reinterpret_cast<const float4*>(&s_probe[3][dbase]);
                const float4 zr4 = *reinterpret_cast<const float4*>(&s_probe[4][dbase]);
                const float4 zr5 = *reinterpret_cast<const float4*>(&s_probe[5][dbase]);
                const float4 zr6 = *reinterpret_cast<const float4*>(&s_probe[6][dbase]);
                const float4 zr7 = *reinterpret_cast<const float4*>(&s_probe[7][dbase]);
                P1STEP(x, 0);
                P1STEP(y, 1);
                P1STEP(z, 2);
                P1STEP(w, 3);
            }

            P1EPI(a00, a01, 0); P1EPI(a10, a11, 1);
            P1EPI(a20, a21, 2); P1EPI(a30, a31, 3);
            P1EPI(a40, a41, 4); P1EPI(a50, a51, 5);
            P1EPI(a60, a61, 6); P1EPI(a70, a71, 7);
            __syncthreads();

            // ---------- phase 2: k = hid @ W2 + b2 ----------
            // thread: 4 rows (4*rg..) x 4 cols (4*icol..), j in its half.
            // Partial sums across j-halves combined via shfl.xor(16).
            ull k00 = 0, k01 = 0, k10 = 0, k11 = 0;
            ull k20 = 0, k21 = 0, k30 = 0, k31 = 0;
            {
                // fold bias into q==0 partial only
                if (q == 0) { k00 = b2p0; k01 = b2p1; k10 = b2p0; k11 = b2p1;
                              k20 = b2p0; k21 = b2p1; k30 = b2p0; k31 = b2p1; }
            }
            const int j0 = q * (Hn / 2);
            #pragma unroll 2
            for (int jj = 0; jj < Hn / 2; jj += 4) {
                const int jbase = j0 + jj;
                const float4 hv0 = *reinterpret_cast<const float4*>(&s_hid[4 * rg + 0][jbase]);
                const float4 hv1 = *reinterpret_cast<const float4*>(&s_hid[4 * rg + 1][jbase]);
                const float4 hv2 = *reinterpret_cast<const float4*>(&s_hid[4 * rg + 2][jbase]);
                const float4 hv3 = *reinterpret_cast<const float4*>(&s_hid[4 * rg + 3][jbase]);
                P2STEP(x, 0);
                P2STEP(y, 1);
                P2STEP(z, 2);
                P2STEP(w, 3);
            }

            // combine the two j-halves (lane ^ 16 holds the partner partial)
            k00 = add2(k00, __shfl_xor_sync(0xffffffffu, k00, 16));
            k01 = add2(k01, __shfl_xor_sync(0xffffffffu, k01, 16));
            k10 = add2(k10, __shfl_xor_sync(0xffffffffu, k10, 16));
            k11 = add2(k11, __shfl_xor_sync(0xffffffffu, k11, 16));
            k20 = add2(k20, __shfl_xor_sync(0xffffffffu, k20, 16));
            k21 = add2(k21, __shfl_xor_sync(0xffffffffu, k21, 16));
            k30 = add2(k30, __shfl_xor_sync(0xffffffffu, k30, 16));
            k31 = add2(k31, __shfl_xor_sync(0xffffffffu, k31, 16));

            float4 kk[4];
            unpk2(k00, kk[0].x, kk[0].y); unpk2(k01, kk[0].z, kk[0].w);
            unpk2(k10, kk[1].x, kk[1].y); unpk2(k11, kk[1].z, kk[1].w);
            unpk2(k20, kk[2].x, kk[2].y); unpk2(k21, kk[2].z, kk[2].w);
            unpk2(k30, kk[3].x, kk[3].y); unpk2(k31, kk[3].z, kk[3].w);

            // ---------- RK4 elementwise glue (registers only) ----------
            #pragma unroll
            for (int r = 0; r < 4; ++r) {
                float4 p;
                if (e == 0) {
                    ac[r] = kk[r];
                    p     = f4_axpy(h2, kk[r], zb[r]);
                } else if (e == 1) {
                    ac[r] = f4_axpy(2.0f, kk[r], ac[r]);
                    p     = f4_axpy(h2, kk[r], zb[r]);
                } else if (e == 2) {
                    ac[r] = f4_axpy(2.0f, kk[r], ac[r]);
                    p     = f4_axpy(h, kk[r], zb[r]);
                } else {
                    ac[r] = f4_add(ac[r], kk[r]);
                    zb[r] = f4_axpy(h6, ac[r], zb[r]);
                    p     = zb[r];
                }
                // both q-lanes write the same value to the same address: benign
                *reinterpret_cast<float4*>(&s_probe[4 * rg + r][4 * icol]) = p;
            }
            __syncthreads();
        }
    }

    if (q == 0) {
        #pragma unroll
        for (int r = 0; r < 4; ++r)
            reinterpret_cast<float4*>(out)[(row0 + 4 * rg + r) * (Dn / 4) + icol] = zb[r];
    }

#undef P1STEP
#undef P1EPI
#undef P2STEP
}

extern "C" void kernel_launch(void* const* d_in, const int* in_sizes, int n_in,
                              void* d_out, int out_size) {
    const float* z0 = (const float*)d_in[0];
    const float* tt = (const float*)d_in[1];
    const float* W1 = (const float*)d_in[2];
    const float* b1 = (const float*)d_in[3];
    const float* W2 = (const float*)d_in[4];
    const float* b2 = (const float*)d_in[5];
    float* out = (float*)d_out;
    (void)in_sizes; (void)n_in; (void)out_size;

    node_rk4_kernel<<<GRID, NTHR>>>(z0, tt, W1, b1, W2, b2, out);
}

// round 7
// speedup vs baseline: 2.2917x; 1.5016x over previous
#include <cuda_runtime.h>

// NeuralODE fused RK4 persistent kernel — minimal-L2-traffic f32x2 version.
// B=1024, D=256, H=1024, 8 RK4 steps (32 MLP evals). 128 CTAs x 512 threads.
//
// Weight traffic per CTA per eval: W1 read exactly once (1 MB) and W2 read
// exactly once (1 MB) — phase-1 d-range split 2-way within each warp,
// phase-2 j-range split 8-way within each warp; partial sums combined with
// shfl-based reduce-scatter so each lane finishes owning one batch row.

namespace {
constexpr int Bn     = 1024;
constexpr int Dn     = 256;
constexpr int Hn     = 1024;
constexpr int NSTEPS = 8;
constexpr int MBLK   = 8;
constexpr int NTHR   = 512;
constexpr int GRID   = Bn / MBLK;   // 128 CTAs
}

using ull = unsigned long long;

__device__ __forceinline__ float tanha(float x) {
    float y;
    asm("tanh.approx.f32 %0, %1;" : "=f"(y) : "f"(x));
    return y;
}

__device__ __forceinline__ ull dup2(float x) {
    ull r;
    asm("mov.b64 %0, {%1, %1};" : "=l"(r) : "f"(x));
    return r;
}

__device__ __forceinline__ ull pk2(float lo, float hi) {
    ull r;
    asm("mov.b64 %0, {%1, %2};" : "=l"(r) : "f"(lo), "f"(hi));
    return r;
}

__device__ __forceinline__ void unpk2(ull p, float& lo, float& hi) {
    asm("mov.b64 {%0, %1}, %2;" : "=f"(lo), "=f"(hi) : "l"(p));
}

__device__ __forceinline__ ull fma2(ull a, ull b, ull c) {
    ull d;
    asm("fma.rn.f32x2 %0, %1, %2, %3;" : "=l"(d) : "l"(a), "l"(b), "l"(c));
    return d;
}

__device__ __forceinline__ ull add2(ull a, ull b) {
    ull d;
    asm("add.rn.f32x2 %0, %1, %2;" : "=l"(d) : "l"(a), "l"(b));
    return d;
}

__device__ __forceinline__ ull shfl_xor64(ull v, int m) {
    return __shfl_xor_sync(0xffffffffu, v, m);
}

__device__ __forceinline__ float4 f4_axpy(float a, float4 x, float4 y) {
    float4 r;
    r.x = fmaf(a, x.x, y.x);
    r.y = fmaf(a, x.y, y.y);
    r.z = fmaf(a, x.z, y.z);
    r.w = fmaf(a, x.w, y.w);
    return r;
}

__device__ __forceinline__ float4 f4_add(float4 a, float4 b) {
    float4 r; r.x = a.x + b.x; r.y = a.y + b.y; r.z = a.z + b.z; r.w = a.w + b.w; return r;
}

__global__ void __launch_bounds__(NTHR, 1) node_rk4_kernel(
    const float* __restrict__ z0, const float* __restrict__ tt,
    const float* __restrict__ W1, const float* __restrict__ b1,
    const float* __restrict__ W2, const float* __restrict__ b2,
    float* __restrict__ out)
{
    __shared__ __align__(16) float s_probe[MBLK][Dn];   //  8 KB
    __shared__ __align__(16) float s_hid[MBLK][Hn];     // 32 KB

    const int tid  = threadIdx.x;
    const int row0 = blockIdx.x * MBLK;

    const float h  = (tt[1] - tt[0]) / (float)NSTEPS;
    const float h2 = 0.5f * h;
    const float h6 = h * (1.0f / 6.0f);

    const int warp = tid >> 5;
    const int lane = tid & 31;

    // phase-1 ownership: d-half q1, H-col float4 index oc (0..255)
    const int q1 = lane >> 4;
    const int oc = warp * 16 + (lane & 15);
    // phase-2 / glue ownership: j-eighth q3 (also glue row), out col icol (0..63)
    const int q3   = (lane >> 2) & 7;
    const int icol = warp * 4 + (lane & 3);

    const ulonglong2* __restrict__ W1u2 = reinterpret_cast<const ulonglong2*>(W1);
    const ulonglong2* __restrict__ W2u2 = reinterpret_cast<const ulonglong2*>(W2);

    // biases (counted exactly once via the q==0 partial)
    const float4 b1v = reinterpret_cast<const float4*>(b1)[oc];
    const ull b1p0 = (q1 == 0) ? pk2(b1v.x, b1v.y) : 0ull;
    const ull b1p1 = (q1 == 0) ? pk2(b1v.z, b1v.w) : 0ull;
    const float4 b2v = reinterpret_cast<const float4*>(b2)[icol];
    const ull b2p0 = (q3 == 0) ? pk2(b2v.x, b2v.y) : 0ull;
    const ull b2p1 = (q3 == 0) ? pk2(b2v.z, b2v.w) : 0ull;

    // glue state: row q3, cols [4*icol, 4*icol+4)
    float4 zb = reinterpret_cast<const float4*>(z0)[(row0 + q3) * (Dn / 4) + icol];
    float4 ac;
    *reinterpret_cast<float4*>(&s_probe[q3][4 * icol]) = zb;
    __syncthreads();

// ---- phase 1 sub-step: one d value ----
#define P1STEP(comp, dof)                                                          \
    do {                                                                           \
        const ulonglong2 wv = W1u2[(dbase + (dof)) * (Hn / 4) + oc];               \
        _Pragma("unroll")                                                          \
        for (int r = 0; r < 8; ++r) {                                              \
            const ull zd = dup2(zr[r].comp);                                       \
            a[r][0] = fma2(zd, wv.x, a[r][0]);                                     \
            a[r][1] = fma2(zd, wv.y, a[r][1]);                                     \
        }                                                                          \
    } while (0)

// ---- phase 2 sub-step: one j value ----
#define P2STEP(comp, jof)                                                          \
    do {                                                                           \
        const ulonglong2 wv = W2u2[(jbase + (jof)) * (Dn / 4) + icol];             \
        _Pragma("unroll")                                                          \
        for (int r = 0; r < 8; ++r) {                                              \
            const ull hd = dup2(hv[r].comp);                                       \
            k[r][0] = fma2(hd, wv.x, k[r][0]);                                     \
            k[r][1] = fma2(hd, wv.y, k[r][1]);                                     \
        }                                                                          \
    } while (0)

    for (int step = 0; step < NSTEPS; ++step) {
        #pragma unroll
        for (int e = 0; e < 4; ++e) {
            // ---------- phase 1: hid = tanh(probe @ W1 + b1) ----------
            // thread: H-cols [4*oc,+4), all 8 rows, d in its half. W1 read once/CTA.
            ull a[8][2];
            #pragma unroll
            for (int r = 0; r < 8; ++r) { a[r][0] = b1p0; a[r][1] = b1p1; }

            #pragma unroll 2
            for (int d4 = 0; d4 < 32; ++d4) {
                const int dbase = q1 * 128 + d4 * 4;
                float4 zr[8];
                #pragma unroll
                for (int r = 0; r < 8; ++r)
                    zr[r] = *reinterpret_cast<const float4*>(&s_probe[r][dbase]);
                P1STEP(x, 0);
                P1STEP(y, 1);
                P1STEP(z, 2);
                P1STEP(w, 3);
            }

            // reduce-scatter over q1 (xor 16): lane keeps rows 4*q1 + i
            ull h4[4][2];
            #pragma unroll
            for (int i = 0; i < 4; ++i) {
                #pragma unroll
                for (int p = 0; p < 2; ++p) {
                    const ull keep = q1 ? a[4 + i][p] : a[i][p];
                    const ull send = q1 ? a[i][p] : a[4 + i][p];
                    h4[i][p] = add2(keep, shfl_xor64(send, 16));
                }
            }

            #pragma unroll
            for (int i = 0; i < 4; ++i) {
                float u0, u1, u2, u3;
                unpk2(h4[i][0], u0, u1);
                unpk2(h4[i][1], u2, u3);
                const float4 tv = make_float4(tanha(u0), tanha(u1), tanha(u2), tanha(u3));
                *reinterpret_cast<float4*>(&s_hid[4 * q1 + i][4 * oc]) = tv;
            }
            __syncthreads();

            // ---------- phase 2: k = hid @ W2 + b2 ----------
            // thread: cols [4*icol,+4), all 8 rows, j in its eighth (interleaved
            // float4 chunks so per-warp s_hid reads are 128B contiguous).
            // W2 read once/CTA.
            ull k[8][2];
            #pragma unroll
            for (int r = 0; r < 8; ++r) { k[r][0] = b2p0; k[r][1] = b2p1; }

            #pragma unroll 2
            for (int j8 = 0; j8 < 32; ++j8) {
                const int jbase = (j8 * 8 + q3) * 4;
                float4 hv[8];
                #pragma unroll
                for (int r = 0; r < 8; ++r)
                    hv[r] = *reinterpret_cast<const float4*>(&s_hid[r][jbase]);
                P2STEP(x, 0);
                P2STEP(y, 1);
                P2STEP(z, 2);
                P2STEP(w, 3);
            }

            // reduce-scatter over q3 (3 rounds); lane ends with row q3.
            const int tA = (q3 >> 2) & 1;
            ull rA[4][2];
            #pragma unroll
            for (int i = 0; i < 4; ++i) {
                #pragma unroll
                for (int p = 0; p < 2; ++p) {
                    const ull keep = tA ? k[4 + i][p] : k[i][p];
                    const ull send = tA ? k[i][p] : k[4 + i][p];
                    rA[i][p] = add2(keep, shfl_xor64(send, 16));
                }
            }
            const int tB = (q3 >> 1) & 1;
            ull rB[2][2];
            #pragma unroll
            for (int u = 0; u < 2; ++u) {
                #pragma unroll
                for (int p = 0; p < 2; ++p) {
                    const ull keep = tB ? rA[2 + u][p] : rA[u][p];
                    const ull send = tB ? rA[u][p] : rA[2 + u][p];
                    rB[u][p] = add2(keep, shfl_xor64(send, 8));
                }
            }
            const int tC = q3 & 1;
            ull rC[2];
            #pragma unroll
            for (int p = 0; p < 2; ++p) {
                const ull keep = tC ? rB[1][p] : rB[0][p];
                const ull send = tC ? rB[0][p] : rB[1][p];
                rC[p] = add2(keep, shfl_xor64(send, 4));
            }

            float4 kk;
            unpk2(rC[0], kk.x, kk.y);
            unpk2(rC[1], kk.z, kk.w);

            // ---------- RK4 elementwise glue (row q3, registers only) ----------
            float4 p;
            if (e == 0) {
                ac = kk;
                p  = f4_axpy(h2, kk, zb);
            } else if (e == 1) {
                ac = f4_axpy(2.0f, kk, ac);
                p  = f4_axpy(h2, kk, zb);
            } else if (e == 2) {
                ac = f4_axpy(2.0f, kk, ac);
                p  = f4_axpy(h, kk, zb);
            } else {
                ac = f4_add(ac, kk);
                zb = f4_axpy(h6, ac, zb);
                p  = zb;
            }
            *reinterpret_cast<float4*>(&s_probe[q3][4 * icol]) = p;
            __syncthreads();
        }
    }

    reinterpret_cast<float4*>(out)[(row0 + q3) * (Dn / 4) + icol] = zb;

#undef P1STEP
#undef P2STEP
}

extern "C" void kernel_launch(void* const* d_in, const int* in_sizes, int n_in,
                              void* d_out, int out_size) {
    const float* z0 = (const float*)d_in[0];
    const float* tt = (const float*)d_in[1];
    const float* W1 = (const float*)d_in[2];
    const float* b1 = (const float*)d_in[3];
    const float* W2 = (const float*)d_in[4];
    const float* b2 = (const float*)d_in[5];
    float* out = (float*)d_out;
    (void)in_sizes; (void)n_in; (void)out_size;

    node_rk4_kernel<<<GRID, NTHR>>>(z0, tt, W1, b1, W2, b2, out);
}